// round 2
// baseline (speedup 1.0000x reference)
#include <cuda_runtime.h>
#include <cstddef>

#define Bc 32
#define Tc 1000
#define Vc 1024
#define Lc 128
#define Sc 257          // 2L+1
#define SP 264          // padded row stride for lp_ext
#define NEGF (-1e30f)

// Scratch: lp_ext[b][t][s] = log_softmax(hs)[b,t,ext[s]]
__device__ float g_lp[(size_t)Bc * Tc * SP];
__device__ float g_loss[Bc];

// ---------------------------------------------------------------------------
// Kernel 1: per (b,t) row — logsumexp over V, gather at extended labels.
// grid = B*T blocks, 256 threads. float4 loads, row cached in smem for gather.
// ---------------------------------------------------------------------------
__global__ void __launch_bounds__(256) k_lse_gather(const float* __restrict__ hs,
                                                    const int* __restrict__ ys)
{
    __shared__ float srow[Vc];
    __shared__ float sw[8];
    __shared__ float sbc;

    const int bt  = blockIdx.x;           // b*T + t
    const int b   = bt / Tc;
    const int tid = threadIdx.x;

    const float4* rp = (const float4*)(hs + (size_t)bt * Vc);
    float4 v = rp[tid];
    ((float4*)srow)[tid] = v;

    // --- max reduction ---
    float m = fmaxf(fmaxf(v.x, v.y), fmaxf(v.z, v.w));
#pragma unroll
    for (int o = 16; o; o >>= 1) m = fmaxf(m, __shfl_xor_sync(0xffffffffu, m, o));
    if ((tid & 31) == 0) sw[tid >> 5] = m;
    __syncthreads();
    if (tid == 0) {
        float mm = sw[0];
#pragma unroll
        for (int i = 1; i < 8; i++) mm = fmaxf(mm, sw[i]);
        sbc = mm;
    }
    __syncthreads();
    const float mx = sbc;

    // --- sum of exp ---
    float s = __expf(v.x - mx) + __expf(v.y - mx) + __expf(v.z - mx) + __expf(v.w - mx);
#pragma unroll
    for (int o = 16; o; o >>= 1) s += __shfl_xor_sync(0xffffffffu, s, o);
    if ((tid & 31) == 0) sw[tid >> 5] = s;
    __syncthreads();
    if (tid == 0) {
        float ss = sw[0];
#pragma unroll
        for (int i = 1; i < 8; i++) ss += sw[i];
        sbc = mx + __logf(ss);
    }
    __syncthreads();
    const float lse = sbc;

    // --- gather at extended labels: even s -> blank(0), odd s -> ys[b][(s-1)/2]
    float* out = g_lp + (size_t)bt * SP;
    if (tid < Sc) {
        int lbl = (tid & 1) ? ys[b * Lc + (tid >> 1)] : 0;
        out[tid] = srow[lbl] - lse;
    }
    if (tid == 0) {
        out[Sc - 1 + 0] = out[Sc - 1];   // no-op safe line avoided; s=256 handled below
    }
    // s = 256 (even -> blank), since blockDim 256 covers s=0..255
    if (tid == 0) {
        out[256] = srow[0] - lse;
    }
}

// ---------------------------------------------------------------------------
// Kernel 2: CTC forward DP. One block per batch, one thread per lattice state.
// Double-buffered shared alpha -> exactly one __syncthreads per time step.
// ---------------------------------------------------------------------------
__global__ void __launch_bounds__(288) k_ctc_dp(const int* __restrict__ ys,
                                                const int* __restrict__ hlens,
                                                const int* __restrict__ ylens)
{
    __shared__ float abuf[2][SP];

    const int b   = blockIdx.x;
    const int tid = threadIdx.x;
    const bool isState = (tid < Sc);

    // skip transition allowed iff s>=2, ext[s]!=blank, ext[s]!=ext[s-2]
    bool skip = false;
    if (isState && tid >= 3 && (tid & 1)) {
        int i  = tid >> 1;                       // label index (>=1 here)
        skip = (ys[b * Lc + i] != ys[b * Lc + i - 1]);
    }

    const int hlen = hlens[b];
    const float* lp = g_lp + (size_t)b * Tc * SP;

    // t = 0 init
    float alpha = NEGF;
    if (tid == 0) alpha = lp[0];
    if (tid == 1) alpha = lp[1];
    if (isState) abuf[0][tid] = alpha;
    __syncthreads();

    int cur = 0;
    float lp_next = isState ? lp[SP + tid] : 0.f;     // t = 1

    for (int t = 1; t < Tc; t++) {
        const float lpt = lp_next;
        if (isState && (t + 1) < Tc)
            lp_next = lp[(size_t)(t + 1) * SP + tid]; // prefetch next step (L2)

        float a1 = alpha;
        float a2 = (isState && tid >= 1) ? abuf[cur][tid - 1] : NEGF;
        float a3 = skip ? abuf[cur][tid - 2] : NEGF;

        float m   = fmaxf(a1, fmaxf(a2, a3));
        float sum = __expf(a1 - m) + __expf(a2 - m) + __expf(a3 - m);
        float na  = m + __logf(sum) + lpt;

        if (isState && t < hlen) alpha = na;

        cur ^= 1;
        if (isState) abuf[cur][tid] = alpha;
        __syncthreads();
    }

    if (tid == 0) {
        int   yl = ylens[b];
        float ab = abuf[cur][2 * yl];
        float al = abuf[cur][2 * yl - 1];
        float m  = fmaxf(ab, al);
        float aend = m + __logf(__expf(ab - m) + __expf(al - m));
        g_loss[b] = -aend / (float)yl;
    }
}

// ---------------------------------------------------------------------------
// Kernel 3: mean over batch -> scalar output.
// ---------------------------------------------------------------------------
__global__ void k_reduce(float* __restrict__ out)
{
    float v = g_loss[threadIdx.x];
#pragma unroll
    for (int o = 16; o; o >>= 1) v += __shfl_xor_sync(0xffffffffu, v, o);
    if (threadIdx.x == 0) out[0] = v / (float)Bc;
}

// ---------------------------------------------------------------------------
extern "C" void kernel_launch(void* const* d_in, const int* in_sizes, int n_in,
                              void* d_out, int out_size)
{
    const float* hs    = (const float*)d_in[0];   // (B,T,V) fp32
    const int*   hlens = (const int*)  d_in[1];   // (B,)
    const int*   ys    = (const int*)  d_in[2];   // (B,L)
    const int*   ylens = (const int*)  d_in[3];   // (B,)
    float* out = (float*)d_out;

    (void)in_sizes; (void)n_in; (void)out_size;

    k_lse_gather<<<Bc * Tc, 256>>>(hs, ys);
    k_ctc_dp<<<Bc, 288>>>(ys, hlens, ylens);
    k_reduce<<<1, 32>>>(out);
}

// round 3
// speedup vs baseline: 2.3320x; 2.3320x over previous
#include <cuda_runtime.h>
#include <cstddef>

#define Bc 32
#define Tc 1000
#define Vc 1024
#define Lc 128
#define Sc 257          // 2L+1
#define SP 264          // padded row stride for lp_ext
#define NEGF (-1e30f)
#define QD 8            // prefetch queue depth (DRAM latency hiding)

// Scratch: lp_ext[b][t][s] = log_softmax(hs)[b,t,ext[s]]
__device__ float g_lp[(size_t)Bc * Tc * SP];
__device__ float g_loss[Bc];

// ---------------------------------------------------------------------------
// Kernel 1: per (b,t) row — logsumexp over V, gather at extended labels.
// ---------------------------------------------------------------------------
__global__ void __launch_bounds__(256) k_lse_gather(const float* __restrict__ hs,
                                                    const int* __restrict__ ys)
{
    __shared__ float srow[Vc];
    __shared__ float sw[8];
    __shared__ float sbc;

    const int bt  = blockIdx.x;           // b*T + t
    const int b   = bt / Tc;
    const int tid = threadIdx.x;

    const float4* rp = (const float4*)(hs + (size_t)bt * Vc);
    float4 v = rp[tid];
    ((float4*)srow)[tid] = v;

    // --- max reduction ---
    float m = fmaxf(fmaxf(v.x, v.y), fmaxf(v.z, v.w));
#pragma unroll
    for (int o = 16; o; o >>= 1) m = fmaxf(m, __shfl_xor_sync(0xffffffffu, m, o));
    if ((tid & 31) == 0) sw[tid >> 5] = m;
    __syncthreads();
    if (tid == 0) {
        float mm = sw[0];
#pragma unroll
        for (int i = 1; i < 8; i++) mm = fmaxf(mm, sw[i]);
        sbc = mm;
    }
    __syncthreads();
    const float mx = sbc;

    // --- sum of exp ---
    float s = __expf(v.x - mx) + __expf(v.y - mx) + __expf(v.z - mx) + __expf(v.w - mx);
#pragma unroll
    for (int o = 16; o; o >>= 1) s += __shfl_xor_sync(0xffffffffu, s, o);
    if ((tid & 31) == 0) sw[tid >> 5] = s;
    __syncthreads();
    if (tid == 0) {
        float ss = sw[0];
#pragma unroll
        for (int i = 1; i < 8; i++) ss += sw[i];
        sbc = mx + __logf(ss);
    }
    __syncthreads();
    const float lse = sbc;

    // --- gather at extended labels: even s -> blank(0), odd s -> ys[b][(s-1)/2]
    float* out = g_lp + (size_t)bt * SP;
    if (tid < Sc) {
        int lbl = (tid & 1) ? ys[b * Lc + (tid >> 1)] : 0;
        out[tid] = srow[lbl] - lse;
    }
    if (tid == 0) {
        out[256] = srow[0] - lse;     // s = 256 (blank), beyond blockDim coverage
    }
}

// ---------------------------------------------------------------------------
// Kernel 2: CTC forward DP. One block/batch, one thread/state.
// Register prefetch queue of depth QD hides DRAM latency on the lp stream.
// Alpha double buffer shifted by +2 so boundary states need no predicates.
// ---------------------------------------------------------------------------
__global__ void __launch_bounds__(288) k_ctc_dp(const int* __restrict__ ys,
                                                const int* __restrict__ hlens,
                                                const int* __restrict__ ylens)
{
    __shared__ float abuf[2][292];      // [0..1] = NEG pad; state s lives at s+2

    const int b   = blockIdx.x;
    const int tid = threadIdx.x;
    const bool isState = (tid < Sc);

    bool skip = false;
    if (isState && tid >= 3 && (tid & 1)) {
        int i  = tid >> 1;
        skip = (ys[b * Lc + i] != ys[b * Lc + i - 1]);
    }

    const int hlen = hlens[b];
    const float* lpp = g_lp + (size_t)b * Tc * SP + tid;   // this thread's lp column

    if (tid < 2) { abuf[0][tid] = NEGF; abuf[1][tid] = NEGF; }

    float alpha = (tid < 2) ? lpp[0] : NEGF;               // t = 0 init
    if (isState) abuf[0][tid + 2] = alpha;
    __syncthreads();

    // Preload queue for t = 1..QD
    float q[QD];
#pragma unroll
    for (int d = 0; d < QD; d++)
        q[d] = isState ? lpp[(size_t)(1 + d) * SP] : NEGF;

    int cur = 0;

    // Main chunks: t = 1 .. 992 (124 chunks of 8); prefetch t+8 (predicated).
    for (int tc = 1; tc <= Tc - 1 - (QD - 1); tc += QD) {
#pragma unroll
        for (int d = 0; d < QD; d++) {
            const int t   = tc + d;
            const float lpt = q[d];
            const int tp  = t + QD;
            q[d] = (isState && tp <= Tc - 1) ? lpp[(size_t)tp * SP] : NEGF;

            float a1 = alpha;
            float a2 = abuf[cur][tid + 1];
            float a3 = skip ? abuf[cur][tid] : NEGF;

            float m   = fmaxf(a1, fmaxf(a2, a3));
            float sum = __expf(a1 - m) + __expf(a2 - m) + __expf(a3 - m);
            float na  = m + __logf(sum) + lpt;

            if (isState && t < hlen) alpha = na;

            cur ^= 1;
            if (isState) abuf[cur][tid + 2] = alpha;
            __syncthreads();
        }
    }

    // Tail: t = 993..999, values already in queue (d = t - 993).
#pragma unroll
    for (int d = 0; d < 7; d++) {
        const int t = (Tc - 7) + d;     // 993..999
        const float lpt = q[d];

        float a1 = alpha;
        float a2 = abuf[cur][tid + 1];
        float a3 = skip ? abuf[cur][tid] : NEGF;

        float m   = fmaxf(a1, fmaxf(a2, a3));
        float sum = __expf(a1 - m) + __expf(a2 - m) + __expf(a3 - m);
        float na  = m + __logf(sum) + lpt;

        if (isState && t < hlen) alpha = na;

        cur ^= 1;
        if (isState) abuf[cur][tid + 2] = alpha;
        __syncthreads();
    }

    if (tid == 0) {
        int   yl = ylens[b];
        float ab = abuf[cur][2 * yl + 2];
        float al = abuf[cur][2 * yl + 1];
        float m  = fmaxf(ab, al);
        float aend = m + __logf(__expf(ab - m) + __expf(al - m));
        g_loss[b] = -aend / (float)yl;
    }
}

// ---------------------------------------------------------------------------
// Kernel 3: mean over batch -> scalar output.
// ---------------------------------------------------------------------------
__global__ void k_reduce(float* __restrict__ out)
{
    float v = g_loss[threadIdx.x];
#pragma unroll
    for (int o = 16; o; o >>= 1) v += __shfl_xor_sync(0xffffffffu, v, o);
    if (threadIdx.x == 0) out[0] = v / (float)Bc;
}

// ---------------------------------------------------------------------------
extern "C" void kernel_launch(void* const* d_in, const int* in_sizes, int n_in,
                              void* d_out, int out_size)
{
    const float* hs    = (const float*)d_in[0];   // (B,T,V) fp32
    const int*   hlens = (const int*)  d_in[1];   // (B,)
    const int*   ys    = (const int*)  d_in[2];   // (B,L)
    const int*   ylens = (const int*)  d_in[3];   // (B,)
    float* out = (float*)d_out;

    (void)in_sizes; (void)n_in; (void)out_size;

    k_lse_gather<<<Bc * Tc, 256>>>(hs, ys);
    k_ctc_dp<<<Bc, 288>>>(ys, hlens, ylens);
    k_reduce<<<1, 32>>>(out);
}

// round 5
// speedup vs baseline: 4.2698x; 1.8309x over previous
#include <cuda_runtime.h>
#include <cstddef>

#define Bc 32
#define Tc 1000
#define Vc 1024
#define Lc 128
#define Sc 257          // 2L+1
#define SP 264          // padded row stride for scratch
#define NEGF (-1e30f)
#define KC 16           // DP steps per chunk (barrier period)
#define NCH 63          // chunks: covers t=1..1008 (tail frozen by t<hlen)
#define LOGV 6.93147180559945f   // ln(1024): probability pre-scale correction

// Scratch: g_p[b][t][s] = softmax prob at extended label s, scaled by V (=1024)
__device__ float g_p[(size_t)Bc * Tc * SP];
__device__ float g_loss[Bc];

// ---------------------------------------------------------------------------
// Kernel 1: per (b,t) row — single-pass softmax + gather at extended labels.
// Stores p * 1024 so the linear-domain DP has per-step decay ~= 1.
// ---------------------------------------------------------------------------
__global__ void __launch_bounds__(256) k_prob(const float* __restrict__ hs,
                                              const int* __restrict__ ys)
{
    __shared__ float se[Vc];
    __shared__ float sw[8];
    __shared__ float sinv;

    const int bt  = blockIdx.x;
    const int b   = bt / Tc;
    const int tid = threadIdx.x;

    float4 v = ((const float4*)(hs + (size_t)bt * Vc))[tid];
    float4 e = make_float4(__expf(v.x), __expf(v.y), __expf(v.z), __expf(v.w));
    ((float4*)se)[tid] = e;

    float s = e.x + e.y + e.z + e.w;
#pragma unroll
    for (int o = 16; o; o >>= 1) s += __shfl_xor_sync(0xffffffffu, s, o);
    if ((tid & 31) == 0) sw[tid >> 5] = s;
    __syncthreads();
    if (tid == 0) {
        float t = sw[0];
#pragma unroll
        for (int i = 1; i < 8; i++) t += sw[i];
        sinv = 1024.0f / t;          // scaled inverse partition
    }
    __syncthreads();

    float* out = g_p + (size_t)bt * SP;
    const float rinv = sinv;
    if (tid < Sc) {
        int lbl = (tid & 1) ? ys[b * Lc + (tid >> 1)] : 0;
        out[tid] = se[lbl] * rinv;
    }
    if (tid == 0) {
        out[256] = se[0] * rinv;     // s=256 (blank)
        out[257] = 0.0f;             // padding state: keep float2 loads clean
    }
}

// ---------------------------------------------------------------------------
// Kernel 2: CTC forward DP, linear domain, warp-private halo chunks.
// 9 warps; lane holds state pair (2i, 2i+1), i = w*16 + l - 16.
// Lanes 0..15 = redundant left halo; lanes 16..31 = owned states.
// One shfl_up per step; barrier + log-domain handoff every KC=16 steps;
// one barrier-free warp renorm mid-chunk bounds fp32 dynamic range.
// ---------------------------------------------------------------------------
__global__ void __launch_bounds__(288) k_ctc_dp(const int* __restrict__ ys,
                                                const int* __restrict__ hlens,
                                                const int* __restrict__ ylens)
{
    __shared__ float sbuf[2][264];     // alpha (log domain) at chunk boundaries

    const int b   = blockIdx.x;
    const int tid = threadIdx.x;
    const int w   = tid >> 5;
    const int l   = tid & 31;
    const int i   = w * 16 + l - 16;           // pair index: states (2i, 2i+1)
    const bool pv  = (i >= 0 && i <= 128);     // even state 2i valid
    const bool ov  = (i >= 0 && i <= 127);     // odd state 2i+1 valid
    const bool own = (l >= 16) && pv;

    // skip for odd state 2i+1 (label i): allowed iff i>=1 and ys[i]!=ys[i-1]
    float skf = 0.f;
    if (i >= 1 && i <= 127)
        skf = (ys[b * Lc + i] != ys[b * Lc + i - 1]) ? 1.f : 0.f;

    const int hlen = hlens[b];
    const float* pc = g_p + ((size_t)b * Tc) * SP + 2 * i;   // deref only when pv

    // t = 0 init (true log domain: undo the 1024 scale)
    if (own) {
        float a0 = (i == 0) ? (__logf(pc[0]) - LOGV) : NEGF;   // state 0
        float a1 = (i == 0) ? (__logf(pc[1]) - LOGV) : NEGF;   // state 1
        sbuf[0][2 * i] = a0;
        if (ov) sbuf[0][2 * i + 1] = a1;
    }
    __syncthreads();

    // Prefetch queue: scaled probs for chunk 0 (t = 1..KC)
    float q[2 * KC];
#pragma unroll
    for (int k = 0; k < KC; k++) {
        int t = 1 + k;
        float2 pq = (pv && t <= Tc - 1) ? *(const float2*)(pc + (size_t)t * SP)
                                        : make_float2(0.f, 0.f);
        q[2 * k] = pq.x; q[2 * k + 1] = pq.y;
    }

    int nb = 0;
    for (int c = 0; c < NCH; c++) {
        // Load boundary alphas (log), renormalize to warp max, go linear
        float ae = pv ? sbuf[nb][2 * i]     : NEGF;
        float ao = ov ? sbuf[nb][2 * i + 1] : NEGF;
        float m = fmaxf(ae, ao);
#pragma unroll
        for (int o = 16; o; o >>= 1) m = fmaxf(m, __shfl_xor_sync(0xffffffffu, m, o));
        m = fmaxf(m, -1e28f);                 // dead-warp guard: exp -> 0
        float Ae = __expf(ae - m);
        float Ao = __expf(ao - m);
        float lc = 0.f;                       // mid-chunk renorm log correction

        const int t0 = 1 + KC * c;
        // scaled steps in this chunk: t in [t0, t0+KC) with t < hlen
        int n_sc = hlen - t0;
        n_sc = (n_sc < 0) ? 0 : (n_sc > KC ? KC : n_sc);

#pragma unroll
        for (int k = 0; k < KC; k++) {
            const int t  = t0 + k;
            const float pe = q[2 * k], po = q[2 * k + 1];
            {   // prefetch same slot for next chunk
                int tp = t + KC;
                float2 pq = (pv && tp <= Tc - 1) ? *(const float2*)(pc + (size_t)tp * SP)
                                                 : make_float2(0.f, 0.f);
                q[2 * k] = pq.x; q[2 * k + 1] = pq.y;
            }
            float fo = __shfl_up_sync(0xffffffffu, Ao, 1);   // A_{2i-1}
            float ne = (Ae + fo) * pe;                        // blank: no skip
            float no = (Ao + Ae + skf * fo) * po;             // label state
            if (t < hlen) { Ae = ne; Ao = no; }               // freeze past hlen

            if (k == 7) {   // barrier-free warp renorm: bound dynamic range
                float wm = fmaxf(Ae, Ao);
#pragma unroll
                for (int o = 16; o; o >>= 1)
                    wm = fmaxf(wm, __shfl_xor_sync(0xffffffffu, wm, o));
                wm = fmaxf(wm, 1e-30f);
                float r = __frcp_rn(wm);
                Ae *= r; Ao *= r;
                lc += __logf(wm);
            }
        }

        // Back to log (undo pre-scale for the scaled steps), publish owned states
        const float corr = m + lc - (float)n_sc * LOGV;
        ae = corr + __logf(fmaxf(Ae, 1e-37f));
        ao = corr + __logf(fmaxf(Ao, 1e-37f));
        nb ^= 1;
        if (own) {
            sbuf[nb][2 * i] = ae;
            if (ov) sbuf[nb][2 * i + 1] = ao;
        }
        __syncthreads();
    }

    if (tid == 0) {
        int   yl  = ylens[b];
        float abk = sbuf[nb][2 * yl];
        float alb = sbuf[nb][2 * yl - 1];
        float mm  = fmaxf(abk, alb);
        float aend = mm + __logf(__expf(abk - mm) + __expf(alb - mm));
        g_loss[b] = -aend / (float)yl;
    }
}

// ---------------------------------------------------------------------------
// Kernel 3: mean over batch -> scalar output.
// ---------------------------------------------------------------------------
__global__ void k_reduce(float* __restrict__ out)
{
    float v = g_loss[threadIdx.x];
#pragma unroll
    for (int o = 16; o; o >>= 1) v += __shfl_xor_sync(0xffffffffu, v, o);
    if (threadIdx.x == 0) out[0] = v / (float)Bc;
}

// ---------------------------------------------------------------------------
extern "C" void kernel_launch(void* const* d_in, const int* in_sizes, int n_in,
                              void* d_out, int out_size)
{
    const float* hs    = (const float*)d_in[0];   // (B,T,V) fp32
    const int*   hlens = (const int*)  d_in[1];   // (B,)
    const int*   ys    = (const int*)  d_in[2];   // (B,L)
    const int*   ylens = (const int*)  d_in[3];   // (B,)
    float* out = (float*)d_out;

    (void)in_sizes; (void)n_in; (void)out_size;

    k_prob<<<Bc * Tc, 256>>>(hs, ys);
    k_ctc_dp<<<Bc, 288>>>(ys, hlens, ylens);
    k_reduce<<<1, 32>>>(out);
}